// round 8
// baseline (speedup 1.0000x reference)
#include <cuda_runtime.h>
#include <cuda_bf16.h>
#include <math.h>

// ---------------------------------------------------------------------------
// NNUE forward pass.
// Inputs (metadata order):
//  0 white_features [8192,12288] f32 (binary 0/1, ~0.25% dense)
//  1 black_features [8192,12288] f32
//  2 side           [8192]       bool -> dtype ambiguous (int32/float32/byte), detected at runtime
//  3 ft_w           [256,12288]  f32
//  4 ft_b           [256]        f32
//  5 l1_w           [32,512]     f32
//  6 l1_b           [32]
//  7 l2_w           [32,32]
//  8 l2_b           [32]
//  9 l3_w           [1,32]
// 10 l3_b           [1]
// Output: [8192] f32 = sigmoid(clip-MLP * 300 / 200)
// ---------------------------------------------------------------------------

#define B_ROWS   8192
#define N_IN     12288
#define H0       256
#define CAP      512        // max active features per row (mean ~31)

// Scratch (device globals: allocation-free rule)
__device__ float g_ftT[(size_t)N_IN * H0];      // 12.6 MB, ft_w transposed
__device__ float g_o0[(size_t)B_ROWS * 512];    // 16 MB, clipped FT outputs
__device__ int   g_side_mode;                   // 0=int32, 1=float32, 2=byte

// ---------------------------------------------------------------------------
// Kernel 0: classify the 'side' buffer's dtype from its raw bits.
// Scan only the first 2048 32-bit words (= 8192 bytes, in-bounds for all cases).
// ---------------------------------------------------------------------------
__global__ void k_detect_side(const unsigned int* side)
{
    __shared__ int okI, okF;
    if (threadIdx.x == 0) { okI = 1; okF = 1; }
    __syncthreads();
    int badI = 0, badF = 0;
    for (int i = threadIdx.x; i < 2048; i += blockDim.x) {
        unsigned int v = side[i];
        if (!(v == 0u || v == 1u))          badI = 1;
        if (!(v == 0u || v == 0x3F800000u)) badF = 1;
    }
    if (badI) okI = 0;
    if (badF) okF = 0;
    __syncthreads();
    if (threadIdx.x == 0)
        g_side_mode = okI ? 0 : (okF ? 1 : 2);
}

// ---------------------------------------------------------------------------
// Kernel 1: tiled transpose ft_w [H0, N_IN] -> g_ftT [N_IN, H0]
// grid (N_IN/32, H0/32), block (32,8), 4 rows per thread.
// ---------------------------------------------------------------------------
__global__ void k_transpose(const float* __restrict__ ft_w)
{
    __shared__ float tile[32][33];
    int bx = blockIdx.x * 32;   // N_IN tile
    int by = blockIdx.y * 32;   // H0 tile
    int tx = threadIdx.x;       // 0..31
    int ty = threadIdx.y;       // 0..7
#pragma unroll
    for (int s = 0; s < 4; s++) {
        int row = by + ty + 8 * s;            // H0 index
        int col = bx + tx;                    // N_IN index
        tile[ty + 8 * s][tx] = ft_w[(size_t)row * N_IN + col];
    }
    __syncthreads();
#pragma unroll
    for (int s = 0; s < 4; s++) {
        int nrow = bx + ty + 8 * s;           // N_IN index
        int hcol = by + tx;                   // H0 index
        g_ftT[(size_t)nrow * H0 + hcol] = tile[tx][ty + 8 * s];
    }
}

// ---------------------------------------------------------------------------
// Kernel 2: sparse feature transformer. One CTA (256 threads) per batch row.
// Phase A: streaming float4 scan of white+black rows -> smem index lists.
// Phase B: thread t accumulates FT lane t over the active columns of g_ftT.
// Clip, side-ordering, write o0.
// ---------------------------------------------------------------------------
__global__ void __launch_bounds__(256) k_feat(
    const float* __restrict__ wf,
    const float* __restrict__ bf,
    const void*  __restrict__ side,
    const float* __restrict__ ft_b)
{
    __shared__ int s_idx_w[CAP];
    __shared__ int s_idx_b[CAP];
    __shared__ int s_cw, s_cb;

    const int r   = blockIdx.x;
    const int tid = threadIdx.x;

    if (tid == 0) { s_cw = 0; s_cb = 0; }
    __syncthreads();

    const float4* w4 = (const float4*)(wf + (size_t)r * N_IN);
    const float4* b4 = (const float4*)(bf + (size_t)r * N_IN);

#pragma unroll
    for (int k = 0; k < 12; k++) {
        int i4 = tid + 256 * k;
        float4 v = __ldcs(&w4[i4]);          // streaming: don't pollute L2
        int j = 4 * i4;
        if (v.x != 0.f) { int c = atomicAdd(&s_cw, 1); if (c < CAP) s_idx_w[c] = j;     }
        if (v.y != 0.f) { int c = atomicAdd(&s_cw, 1); if (c < CAP) s_idx_w[c] = j + 1; }
        if (v.z != 0.f) { int c = atomicAdd(&s_cw, 1); if (c < CAP) s_idx_w[c] = j + 2; }
        if (v.w != 0.f) { int c = atomicAdd(&s_cw, 1); if (c < CAP) s_idx_w[c] = j + 3; }
        float4 u = __ldcs(&b4[i4]);
        if (u.x != 0.f) { int c = atomicAdd(&s_cb, 1); if (c < CAP) s_idx_b[c] = j;     }
        if (u.y != 0.f) { int c = atomicAdd(&s_cb, 1); if (c < CAP) s_idx_b[c] = j + 1; }
        if (u.z != 0.f) { int c = atomicAdd(&s_cb, 1); if (c < CAP) s_idx_b[c] = j + 2; }
        if (u.w != 0.f) { int c = atomicAdd(&s_cb, 1); if (c < CAP) s_idx_b[c] = j + 3; }
    }
    __syncthreads();

    const int cw = min(s_cw, CAP);
    const int cb = min(s_cb, CAP);

    float bias = ft_b[tid];
    float aw = bias, ab = bias;

    // Accumulate active columns (coalesced 1KB loads from L2-resident g_ftT).
    int n = 0;
    for (; n + 4 <= cw; n += 4) {
        float x0 = g_ftT[(size_t)s_idx_w[n + 0] * H0 + tid];
        float x1 = g_ftT[(size_t)s_idx_w[n + 1] * H0 + tid];
        float x2 = g_ftT[(size_t)s_idx_w[n + 2] * H0 + tid];
        float x3 = g_ftT[(size_t)s_idx_w[n + 3] * H0 + tid];
        aw += (x0 + x1) + (x2 + x3);
    }
    for (; n < cw; n++) aw += g_ftT[(size_t)s_idx_w[n] * H0 + tid];

    n = 0;
    for (; n + 4 <= cb; n += 4) {
        float x0 = g_ftT[(size_t)s_idx_b[n + 0] * H0 + tid];
        float x1 = g_ftT[(size_t)s_idx_b[n + 1] * H0 + tid];
        float x2 = g_ftT[(size_t)s_idx_b[n + 2] * H0 + tid];
        float x3 = g_ftT[(size_t)s_idx_b[n + 3] * H0 + tid];
        ab += (x0 + x1) + (x2 + x3);
    }
    for (; n < cb; n++) ab += g_ftT[(size_t)s_idx_b[n] * H0 + tid];

    aw = fminf(fmaxf(aw, 0.f), 1.f);
    ab = fminf(fmaxf(ab, 0.f), 1.f);

    // side ordering: side -> [white, black] else [black, white]
    bool s;
    int mode = g_side_mode;
    if (mode == 0)      s = ((const int*)side)[r] != 0;
    else if (mode == 1) s = ((const float*)side)[r] != 0.f;
    else                s = ((const unsigned char*)side)[r] != 0;

    float* o = g_o0 + (size_t)r * 512;
    if (s) { o[tid] = aw; o[256 + tid] = ab; }
    else   { o[tid] = ab; o[256 + tid] = aw; }
}

// ---------------------------------------------------------------------------
// Kernel 3: MLP head. 512 CTAs x 128 threads; 16 rows/CTA, 4 rows/warp.
// l1_w transposed into padded smem (conflict-free); 4 rows staged interleaved
// so one LDS.128 broadcast feeds 4 FMAs per weight load.
// ---------------------------------------------------------------------------
__global__ void __launch_bounds__(128) k_mlp(
    const float* __restrict__ l1_w, const float* __restrict__ l1_b,
    const float* __restrict__ l2_w, const float* __restrict__ l2_b,
    const float* __restrict__ l3_w, const float* __restrict__ l3_b,
    float* __restrict__ out)
{
    extern __shared__ float sm[];
    float* l1T   = sm;                        // [512][33] = 16896 floats
    float* l2T   = sm + 512 * 33;             // [32][33]  = 1056 floats
    float* stage = sm + 512 * 33 + 32 * 33;   // 4 warps * 512*4 floats

    const int tid  = threadIdx.x;
    const int warp = tid >> 5;
    const int lane = tid & 31;

    // Load l1_w [32,512] into smem transposed: l1T[i*33 + h] = l1_w[h*512 + i]
    for (int idx = tid; idx < 32 * 512; idx += 128) {
        int h = idx >> 9;         // /512
        int i = idx & 511;
        l1T[i * 33 + h] = l1_w[idx];
    }
    for (int idx = tid; idx < 32 * 32; idx += 128) {
        int h = idx >> 5;
        int i = idx & 31;
        l2T[i * 33 + h] = l2_w[idx];
    }
    __syncthreads();

    float* st = stage + warp * 512 * 4;
    const int rowBase = blockIdx.x * 16 + warp * 4;

    // Stage 4 rows of o0 interleaved: st[i*4 + r] = o0[row_r][i]
#pragma unroll
    for (int rr = 0; rr < 4; rr++) {
        const float* src = g_o0 + (size_t)(rowBase + rr) * 512;
#pragma unroll
        for (int k = 0; k < 16; k++) {
            int i = lane + 32 * k;
            st[i * 4 + rr] = src[i];
        }
    }
    __syncwarp();

    const int h = lane;      // each lane owns hidden unit h

    // Layer 1: o1[h] = clip(sum_i l1_w[h,i]*o0[i] + b)
    float b1 = l1_b[h];
    float a0 = b1, a1 = b1, a2 = b1, a3 = b1;
#pragma unroll 4
    for (int i = 0; i < 512; i++) {
        float w = l1T[i * 33 + h];                 // conflict-free
        float4 v = *(const float4*)(st + i * 4);   // uniform-address broadcast
        a0 = fmaf(w, v.x, a0);
        a1 = fmaf(w, v.y, a1);
        a2 = fmaf(w, v.z, a2);
        a3 = fmaf(w, v.w, a3);
    }
    a0 = fminf(fmaxf(a0, 0.f), 1.f);
    a1 = fminf(fmaxf(a1, 0.f), 1.f);
    a2 = fminf(fmaxf(a2, 0.f), 1.f);
    a3 = fminf(fmaxf(a3, 0.f), 1.f);

    // Layer 2: o2[h] = clip(sum_i l2_w[h,i]*o1[i] + b); o1[i] lives in lane i
    float b2 = l2_b[h];
    float c0 = b2, c1 = b2, c2 = b2, c3 = b2;
#pragma unroll
    for (int i = 0; i < 32; i++) {
        float w = l2T[i * 33 + h];
        c0 = fmaf(w, __shfl_sync(0xffffffffu, a0, i), c0);
        c1 = fmaf(w, __shfl_sync(0xffffffffu, a1, i), c1);
        c2 = fmaf(w, __shfl_sync(0xffffffffu, a2, i), c2);
        c3 = fmaf(w, __shfl_sync(0xffffffffu, a3, i), c3);
    }
    c0 = fminf(fmaxf(c0, 0.f), 1.f);
    c1 = fminf(fmaxf(c1, 0.f), 1.f);
    c2 = fminf(fmaxf(c2, 0.f), 1.f);
    c3 = fminf(fmaxf(c3, 0.f), 1.f);

    // Layer 3 + sigmoid
    float w3 = l3_w[h];
    float t0 = w3 * c0, t1 = w3 * c1, t2 = w3 * c2, t3 = w3 * c3;
#pragma unroll
    for (int off = 16; off > 0; off >>= 1) {
        t0 += __shfl_xor_sync(0xffffffffu, t0, off);
        t1 += __shfl_xor_sync(0xffffffffu, t1, off);
        t2 += __shfl_xor_sync(0xffffffffu, t2, off);
        t3 += __shfl_xor_sync(0xffffffffu, t3, off);
    }
    if (lane == 0) {
        float b3 = l3_b[0];
        // sigmoid((x+b)*300/200)
        float x0 = (t0 + b3) * 1.5f;
        float x1 = (t1 + b3) * 1.5f;
        float x2 = (t2 + b3) * 1.5f;
        float x3 = (t3 + b3) * 1.5f;
        out[rowBase + 0] = 1.f / (1.f + expf(-x0));
        out[rowBase + 1] = 1.f / (1.f + expf(-x1));
        out[rowBase + 2] = 1.f / (1.f + expf(-x2));
        out[rowBase + 3] = 1.f / (1.f + expf(-x3));
    }
}

// ---------------------------------------------------------------------------
extern "C" void kernel_launch(void* const* d_in, const int* in_sizes, int n_in,
                              void* d_out, int out_size)
{
    const float* wf   = (const float*)d_in[0];
    const float* bf   = (const float*)d_in[1];
    const void*  side = d_in[2];
    const float* ft_w = (const float*)d_in[3];
    const float* ft_b = (const float*)d_in[4];
    const float* l1_w = (const float*)d_in[5];
    const float* l1_b = (const float*)d_in[6];
    const float* l2_w = (const float*)d_in[7];
    const float* l2_b = (const float*)d_in[8];
    const float* l3_w = (const float*)d_in[9];
    const float* l3_b = (const float*)d_in[10];
    float* out = (float*)d_out;

    // Idempotent; called every time (no static guards per harness rules).
    const int mlp_smem = (512 * 33 + 32 * 33 + 4 * 512 * 4) * (int)sizeof(float);
    cudaFuncSetAttribute(k_mlp, cudaFuncAttributeMaxDynamicSharedMemorySize, mlp_smem);

    k_detect_side<<<1, 256>>>((const unsigned int*)side);

    dim3 tgrid(N_IN / 32, H0 / 32);
    dim3 tblk(32, 8);
    k_transpose<<<tgrid, tblk>>>(ft_w);

    k_feat<<<B_ROWS, 256>>>(wf, bf, side, ft_b);

    k_mlp<<<B_ROWS / 16, 128, mlp_smem>>>(l1_w, l1_b, l2_w, l2_b, l3_w, l3_b, out);
}

// round 12
// speedup vs baseline: 1.0700x; 1.0700x over previous
#include <cuda_runtime.h>
#include <cuda_bf16.h>
#include <math.h>

// ---------------------------------------------------------------------------
// NNUE forward pass, fused.
//  0 white_features [8192,12288] f32 (binary, ~0.25% dense)
//  1 black_features [8192,12288] f32
//  2 side           [8192]       bool (dtype detected at runtime)
//  3 ft_w [256,12288]  4 ft_b[256]
//  5 l1_w [32,512]     6 l1_b[32]
//  7 l2_w [32,32]      8 l2_b[32]
//  9 l3_w [1,32]      10 l3_b[1]
// Output: [8192] f32 = sigmoid(clip-MLP * 300 / 200)
//
// R8 profile: k_mlp was 48.5us at occ 12%/issue 20% (latency-bound, 102KB smem).
// Fix: MLP fused into the feature kernel tail; o0 never touches gmem.
// ---------------------------------------------------------------------------

#define B_ROWS   8192
#define N_IN     12288
#define H0       256
#define CAP      512        // max active features per row (mean ~31)

// Scratch (device globals: allocation-free rule)
__device__ float g_ftT[(size_t)N_IN * H0];   // 12.6 MB, ft_w transposed
__device__ float g_l1T[512 * 32];            // 64 KB, l1_w transposed (L1-resident)
__device__ float g_l2T[32 * 32];             // 4 KB,  l2_w transposed
__device__ int   g_side_mode;                // 0=int32, 1=float32, 2=byte

// ---------------------------------------------------------------------------
// Kernel 0: side-dtype detection + l1/l2 weight transposes (one CTA).
// ---------------------------------------------------------------------------
__global__ void k_prep(const unsigned int* side,
                       const float* __restrict__ l1_w,
                       const float* __restrict__ l2_w)
{
    __shared__ int okI, okF;
    if (threadIdx.x == 0) { okI = 1; okF = 1; }
    __syncthreads();
    int badI = 0, badF = 0;
    for (int i = threadIdx.x; i < 2048; i += blockDim.x) {
        unsigned int v = side[i];           // 8192 bytes: in-bounds for all dtypes
        if (!(v == 0u || v == 1u))          badI = 1;
        if (!(v == 0u || v == 0x3F800000u)) badF = 1;
    }
    if (badI) okI = 0;
    if (badF) okF = 0;
    __syncthreads();
    if (threadIdx.x == 0)
        g_side_mode = okI ? 0 : (okF ? 1 : 2);

    // l1_w [32,512] -> g_l1T[i*32 + h]
    for (int idx = threadIdx.x; idx < 32 * 512; idx += blockDim.x) {
        int h = idx >> 9;
        int i = idx & 511;
        g_l1T[i * 32 + h] = l1_w[idx];
    }
    // l2_w [32,32] -> g_l2T[i*32 + h]
    for (int idx = threadIdx.x; idx < 32 * 32; idx += blockDim.x) {
        int h = idx >> 5;
        int i = idx & 31;
        g_l2T[i * 32 + h] = l2_w[idx];
    }
}

// ---------------------------------------------------------------------------
// Kernel 1: tiled transpose ft_w [H0, N_IN] -> g_ftT [N_IN, H0]
// ---------------------------------------------------------------------------
__global__ void k_transpose(const float* __restrict__ ft_w)
{
    __shared__ float tile[32][33];
    int bx = blockIdx.x * 32;   // N_IN tile
    int by = blockIdx.y * 32;   // H0 tile
    int tx = threadIdx.x;
    int ty = threadIdx.y;
#pragma unroll
    for (int s = 0; s < 4; s++)
        tile[ty + 8 * s][tx] = ft_w[(size_t)(by + ty + 8 * s) * N_IN + (bx + tx)];
    __syncthreads();
#pragma unroll
    for (int s = 0; s < 4; s++)
        g_ftT[(size_t)(bx + ty + 8 * s) * H0 + (by + tx)] = tile[tx][ty + 8 * s];
}

// ---------------------------------------------------------------------------
// Kernel 2: fused feature transformer + MLP head. One CTA (256 thr) per row.
//  A: streaming float4 scan of white+black rows -> smem index lists
//  B: thread t accumulates FT lane t over active columns of g_ftT; clip; side
//     ordering -> s_o0[512] in smem (no gmem round trip)
//  C: layer1 partial dots (8 warps x 64 inputs, lane = output unit,
//     coalesced L1-hit loads from g_l1T), combine; layers 2/3 + sigmoid in
//     warp 0; write out[r].
// ---------------------------------------------------------------------------
__global__ void __launch_bounds__(256) k_fused(
    const float* __restrict__ wf,
    const float* __restrict__ bf,
    const void*  __restrict__ side,
    const float* __restrict__ ft_b,
    const float* __restrict__ l1_b,
    const float* __restrict__ l2_b,
    const float* __restrict__ l3_w,
    const float* __restrict__ l3_b,
    float* __restrict__ out)
{
    __shared__ int   s_idx_w[CAP];
    __shared__ int   s_idx_b[CAP];
    __shared__ int   s_cw, s_cb;
    __shared__ float s_o0[512];
    __shared__ float s_part[8 * 32];

    const int r   = blockIdx.x;
    const int tid = threadIdx.x;

    if (tid == 0) { s_cw = 0; s_cb = 0; }
    __syncthreads();

    // ---- Phase A: sparsify ----
    const float4* w4 = (const float4*)(wf + (size_t)r * N_IN);
    const float4* b4 = (const float4*)(bf + (size_t)r * N_IN);

#pragma unroll
    for (int k = 0; k < 12; k++) {
        int i4 = tid + 256 * k;
        float4 v = __ldcs(&w4[i4]);          // streaming: don't pollute L2
        int j = 4 * i4;
        if (v.x != 0.f) { int c = atomicAdd(&s_cw, 1); if (c < CAP) s_idx_w[c] = j;     }
        if (v.y != 0.f) { int c = atomicAdd(&s_cw, 1); if (c < CAP) s_idx_w[c] = j + 1; }
        if (v.z != 0.f) { int c = atomicAdd(&s_cw, 1); if (c < CAP) s_idx_w[c] = j + 2; }
        if (v.w != 0.f) { int c = atomicAdd(&s_cw, 1); if (c < CAP) s_idx_w[c] = j + 3; }
        float4 u = __ldcs(&b4[i4]);
        if (u.x != 0.f) { int c = atomicAdd(&s_cb, 1); if (c < CAP) s_idx_b[c] = j;     }
        if (u.y != 0.f) { int c = atomicAdd(&s_cb, 1); if (c < CAP) s_idx_b[c] = j + 1; }
        if (u.z != 0.f) { int c = atomicAdd(&s_cb, 1); if (c < CAP) s_idx_b[c] = j + 2; }
        if (u.w != 0.f) { int c = atomicAdd(&s_cb, 1); if (c < CAP) s_idx_b[c] = j + 3; }
    }
    __syncthreads();

    const int cw = min(s_cw, CAP);
    const int cb = min(s_cb, CAP);

    // ---- Phase B: sparse FT accumulate (coalesced 1KB columns, L2-resident) ----
    float bias = ft_b[tid];
    float aw = bias, ab = bias;

    int n = 0;
    for (; n + 4 <= cw; n += 4) {
        float x0 = g_ftT[(size_t)s_idx_w[n + 0] * H0 + tid];
        float x1 = g_ftT[(size_t)s_idx_w[n + 1] * H0 + tid];
        float x2 = g_ftT[(size_t)s_idx_w[n + 2] * H0 + tid];
        float x3 = g_ftT[(size_t)s_idx_w[n + 3] * H0 + tid];
        aw += (x0 + x1) + (x2 + x3);
    }
    for (; n < cw; n++) aw += g_ftT[(size_t)s_idx_w[n] * H0 + tid];

    n = 0;
    for (; n + 4 <= cb; n += 4) {
        float x0 = g_ftT[(size_t)s_idx_b[n + 0] * H0 + tid];
        float x1 = g_ftT[(size_t)s_idx_b[n + 1] * H0 + tid];
        float x2 = g_ftT[(size_t)s_idx_b[n + 2] * H0 + tid];
        float x3 = g_ftT[(size_t)s_idx_b[n + 3] * H0 + tid];
        ab += (x0 + x1) + (x2 + x3);
    }
    for (; n < cb; n++) ab += g_ftT[(size_t)s_idx_b[n] * H0 + tid];

    aw = fminf(fmaxf(aw, 0.f), 1.f);
    ab = fminf(fmaxf(ab, 0.f), 1.f);

    bool s;
    {
        int mode = g_side_mode;
        if (mode == 0)      s = ((const int*)side)[r] != 0;
        else if (mode == 1) s = ((const float*)side)[r] != 0.f;
        else                s = ((const unsigned char*)side)[r] != 0;
    }
    s_o0[tid]       = s ? aw : ab;
    s_o0[256 + tid] = s ? ab : aw;
    __syncthreads();

    // ---- Phase C: MLP head ----
    const int warp = tid >> 5;
    const int lane = tid & 31;

    // Layer 1 partials: warp w covers inputs [w*64, w*64+64); lane = output h.
    // g_l1T loads are coalesced 128B and L1-resident (64KB table reused by all
    // CTAs on the SM); s_o0[i] is a uniform-address smem broadcast.
    {
        float p = 0.f;
        const int base = warp * 64;
#pragma unroll 8
        for (int k = 0; k < 64; k++) {
            int i = base + k;
            p = fmaf(g_l1T[i * 32 + lane], s_o0[i], p);
        }
        s_part[warp * 32 + lane] = p;
    }
    __syncthreads();

    if (warp == 0) {
        // combine 8 partials (conflict-free LDS)
        float sum = l1_b[lane];
#pragma unroll
        for (int j = 0; j < 8; j++) sum += s_part[j * 32 + lane];
        float a = fminf(fmaxf(sum, 0.f), 1.f);      // o1[lane]

        // Layer 2: lane h accumulates over i via shfl broadcast; g_l2T coalesced
        float c = 0.f;
#pragma unroll
        for (int i = 0; i < 32; i++)
            c = fmaf(g_l2T[i * 32 + lane], __shfl_sync(0xffffffffu, a, i), c);
        c = fminf(fmaxf(c + l2_b[lane], 0.f), 1.f); // o2[lane]

        // Layer 3 + sigmoid
        float t = l3_w[lane] * c;
#pragma unroll
        for (int off = 16; off > 0; off >>= 1)
            t += __shfl_xor_sync(0xffffffffu, t, off);
        if (lane == 0)
            out[r] = 1.f / (1.f + expf(-(t + l3_b[0]) * 1.5f));
    }
}

// ---------------------------------------------------------------------------
extern "C" void kernel_launch(void* const* d_in, const int* in_sizes, int n_in,
                              void* d_out, int out_size)
{
    const float* wf   = (const float*)d_in[0];
    const float* bf   = (const float*)d_in[1];
    const void*  side = d_in[2];
    const float* ft_w = (const float*)d_in[3];
    const float* ft_b = (const float*)d_in[4];
    const float* l1_w = (const float*)d_in[5];
    const float* l1_b = (const float*)d_in[6];
    const float* l2_w = (const float*)d_in[7];
    const float* l2_b = (const float*)d_in[8];
    const float* l3_w = (const float*)d_in[9];
    const float* l3_b = (const float*)d_in[10];
    float* out = (float*)d_out;

    k_prep<<<1, 256>>>((const unsigned int*)side, l1_w, l2_w);

    dim3 tgrid(N_IN / 32, H0 / 32);
    dim3 tblk(32, 8);
    k_transpose<<<tgrid, tblk>>>(ft_w);

    k_fused<<<B_ROWS, 256>>>(wf, bf, side, ft_b, l1_b, l2_b, l3_w, l3_b, out);
}

// round 14
// speedup vs baseline: 1.1269x; 1.0532x over previous
#include <cuda_runtime.h>
#include <cuda_bf16.h>
#include <math.h>

// ---------------------------------------------------------------------------
// NNUE forward pass, fused.
//  0 white_features [8192,12288] f32 (binary, ~0.25% dense)
//  1 black_features [8192,12288] f32
//  2 side           [8192]       bool (dtype detected at runtime)
//  3 ft_w [256,12288]  4 ft_b[256]
//  5 l1_w [32,512]     6 l1_b[32]
//  7 l2_w [32,32]      8 l2_b[32]
//  9 l3_w [1,32]      10 l3_b[1]
// Output: [8192] f32 = sigmoid(clip-MLP * 300 / 200)
//
// R8:  k_mlp 48.5us latency-bound -> fused MLP into feature kernel (R12: -12us).
// R12: k_prep measured 17.3us, grid=1, issue 5.5% -> single-CTA latency chain.
//      Fix: spread prep over 18 independent CTAs.
// ---------------------------------------------------------------------------

#define B_ROWS   8192
#define N_IN     12288
#define H0       256
#define CAP      512        // max active features per row (mean ~31)

// Scratch (device globals: allocation-free rule)
__device__ float g_ftT[(size_t)N_IN * H0];   // 12.6 MB, ft_w transposed
__device__ float g_l1T[512 * 32];            // 64 KB, l1_w transposed (L1-resident)
__device__ float g_l2T[32 * 32];             // 4 KB,  l2_w transposed
__device__ int   g_side_mode;                // 0=int32, 1=float32, 2=byte

// ---------------------------------------------------------------------------
// Kernel 0: prep, parallelized over 18 CTAs (R12 fix).
//  blocks 0..15 : l1_w [32,512] -> g_l1T[i*32+h], 1024 elems each,
//                 coalesced writes (thread walks the OUTPUT index).
//  block  16    : l2_w [32,32]  -> g_l2T
//  block  17    : side-dtype detection (one CTA, 2048 words, 8/thread)
// ---------------------------------------------------------------------------
__global__ void __launch_bounds__(256) k_prep(const unsigned int* side,
                       const float* __restrict__ l1_w,
                       const float* __restrict__ l2_w)
{
    const int b   = blockIdx.x;
    const int tid = threadIdx.x;

    if (b < 16) {
        // l1T chunk: output indices [b*1024, (b+1)*1024)
        int base = b * 1024;
#pragma unroll
        for (int k = 0; k < 4; k++) {
            int oidx = base + tid + 256 * k;     // g_l1T linear index
            int h = oidx & 31;
            int i = oidx >> 5;
            g_l1T[oidx] = l1_w[h * 512 + i];
        }
    } else if (b == 16) {
        // l2T: 1024 elements
        int oidx = tid * 4;
#pragma unroll
        for (int k = 0; k < 4; k++) {
            int o = oidx + k;
            int h = o & 31;
            int i = o >> 5;
            g_l2T[o] = l2_w[h * 32 + i];
        }
    } else {
        // side dtype detect: scan first 2048 words (8192 B, in-bounds all dtypes)
        __shared__ int okI, okF;
        if (tid == 0) { okI = 1; okF = 1; }
        __syncthreads();
        int badI = 0, badF = 0;
#pragma unroll
        for (int k = 0; k < 8; k++) {
            unsigned int v = side[tid + 256 * k];
            if (!(v == 0u || v == 1u))          badI = 1;
            if (!(v == 0u || v == 0x3F800000u)) badF = 1;
        }
        if (badI) okI = 0;
        if (badF) okF = 0;
        __syncthreads();
        if (tid == 0)
            g_side_mode = okI ? 0 : (okF ? 1 : 2);
    }
}

// ---------------------------------------------------------------------------
// Kernel 1: tiled transpose ft_w [H0, N_IN] -> g_ftT [N_IN, H0]
// ---------------------------------------------------------------------------
__global__ void k_transpose(const float* __restrict__ ft_w)
{
    __shared__ float tile[32][33];
    int bx = blockIdx.x * 32;   // N_IN tile
    int by = blockIdx.y * 32;   // H0 tile
    int tx = threadIdx.x;
    int ty = threadIdx.y;
#pragma unroll
    for (int s = 0; s < 4; s++)
        tile[ty + 8 * s][tx] = ft_w[(size_t)(by + ty + 8 * s) * N_IN + (bx + tx)];
    __syncthreads();
#pragma unroll
    for (int s = 0; s < 4; s++)
        g_ftT[(size_t)(bx + ty + 8 * s) * H0 + (by + tx)] = tile[tx][ty + 8 * s];
}

// ---------------------------------------------------------------------------
// Kernel 2: fused feature transformer + MLP head. One CTA (256 thr) per row.
//  A: streaming float4 scan of white+black rows -> smem index lists
//  B: thread t accumulates FT lane t over active columns of g_ftT; clip; side
//     ordering -> s_o0[512] in smem (no gmem round trip)
//  C: layer1 partial dots (8 warps x 64 inputs, lane = output unit,
//     coalesced L1-hit loads from g_l1T), combine; layers 2/3 + sigmoid in
//     warp 0; write out[r].
// ---------------------------------------------------------------------------
__global__ void __launch_bounds__(256) k_fused(
    const float* __restrict__ wf,
    const float* __restrict__ bf,
    const void*  __restrict__ side,
    const float* __restrict__ ft_b,
    const float* __restrict__ l1_b,
    const float* __restrict__ l2_b,
    const float* __restrict__ l3_w,
    const float* __restrict__ l3_b,
    float* __restrict__ out)
{
    __shared__ int   s_idx_w[CAP];
    __shared__ int   s_idx_b[CAP];
    __shared__ int   s_cw, s_cb;
    __shared__ float s_o0[512];
    __shared__ float s_part[8 * 32];

    const int r   = blockIdx.x;
    const int tid = threadIdx.x;

    if (tid == 0) { s_cw = 0; s_cb = 0; }
    __syncthreads();

    // ---- Phase A: sparsify ----
    const float4* w4 = (const float4*)(wf + (size_t)r * N_IN);
    const float4* b4 = (const float4*)(bf + (size_t)r * N_IN);

#pragma unroll
    for (int k = 0; k < 12; k++) {
        int i4 = tid + 256 * k;
        float4 v = __ldcs(&w4[i4]);          // streaming: don't pollute L2
        int j = 4 * i4;
        if (v.x != 0.f) { int c = atomicAdd(&s_cw, 1); if (c < CAP) s_idx_w[c] = j;     }
        if (v.y != 0.f) { int c = atomicAdd(&s_cw, 1); if (c < CAP) s_idx_w[c] = j + 1; }
        if (v.z != 0.f) { int c = atomicAdd(&s_cw, 1); if (c < CAP) s_idx_w[c] = j + 2; }
        if (v.w != 0.f) { int c = atomicAdd(&s_cw, 1); if (c < CAP) s_idx_w[c] = j + 3; }
        float4 u = __ldcs(&b4[i4]);
        if (u.x != 0.f) { int c = atomicAdd(&s_cb, 1); if (c < CAP) s_idx_b[c] = j;     }
        if (u.y != 0.f) { int c = atomicAdd(&s_cb, 1); if (c < CAP) s_idx_b[c] = j + 1; }
        if (u.z != 0.f) { int c = atomicAdd(&s_cb, 1); if (c < CAP) s_idx_b[c] = j + 2; }
        if (u.w != 0.f) { int c = atomicAdd(&s_cb, 1); if (c < CAP) s_idx_b[c] = j + 3; }
    }
    __syncthreads();

    const int cw = min(s_cw, CAP);
    const int cb = min(s_cb, CAP);

    // ---- Phase B: sparse FT accumulate (coalesced 1KB columns, L2-resident) ----
    float bias = ft_b[tid];
    float aw = bias, ab = bias;

    int n = 0;
    for (; n + 4 <= cw; n += 4) {
        float x0 = g_ftT[(size_t)s_idx_w[n + 0] * H0 + tid];
        float x1 = g_ftT[(size_t)s_idx_w[n + 1] * H0 + tid];
        float x2 = g_ftT[(size_t)s_idx_w[n + 2] * H0 + tid];
        float x3 = g_ftT[(size_t)s_idx_w[n + 3] * H0 + tid];
        aw += (x0 + x1) + (x2 + x3);
    }
    for (; n < cw; n++) aw += g_ftT[(size_t)s_idx_w[n] * H0 + tid];

    n = 0;
    for (; n + 4 <= cb; n += 4) {
        float x0 = g_ftT[(size_t)s_idx_b[n + 0] * H0 + tid];
        float x1 = g_ftT[(size_t)s_idx_b[n + 1] * H0 + tid];
        float x2 = g_ftT[(size_t)s_idx_b[n + 2] * H0 + tid];
        float x3 = g_ftT[(size_t)s_idx_b[n + 3] * H0 + tid];
        ab += (x0 + x1) + (x2 + x3);
    }
    for (; n < cb; n++) ab += g_ftT[(size_t)s_idx_b[n] * H0 + tid];

    aw = fminf(fmaxf(aw, 0.f), 1.f);
    ab = fminf(fmaxf(ab, 0.f), 1.f);

    bool s;
    {
        int mode = g_side_mode;
        if (mode == 0)      s = ((const int*)side)[r] != 0;
        else if (mode == 1) s = ((const float*)side)[r] != 0.f;
        else                s = ((const unsigned char*)side)[r] != 0;
    }
    s_o0[tid]       = s ? aw : ab;
    s_o0[256 + tid] = s ? ab : aw;
    __syncthreads();

    // ---- Phase C: MLP head ----
    const int warp = tid >> 5;
    const int lane = tid & 31;

    // Layer 1 partials: warp w covers inputs [w*64, w*64+64); lane = output h.
    {
        float p = 0.f;
        const int base = warp * 64;
#pragma unroll 8
        for (int k = 0; k < 64; k++) {
            int i = base + k;
            p = fmaf(g_l1T[i * 32 + lane], s_o0[i], p);
        }
        s_part[warp * 32 + lane] = p;
    }
    __syncthreads();

    if (warp == 0) {
        // combine 8 partials (conflict-free LDS)
        float sum = l1_b[lane];
#pragma unroll
        for (int j = 0; j < 8; j++) sum += s_part[j * 32 + lane];
        float a = fminf(fmaxf(sum, 0.f), 1.f);      // o1[lane]

        // Layer 2: lane h accumulates over i via shfl broadcast; g_l2T coalesced
        float c = 0.f;
#pragma unroll
        for (int i = 0; i < 32; i++)
            c = fmaf(g_l2T[i * 32 + lane], __shfl_sync(0xffffffffu, a, i), c);
        c = fminf(fmaxf(c + l2_b[lane], 0.f), 1.f); // o2[lane]

        // Layer 3 + sigmoid
        float t = l3_w[lane] * c;
#pragma unroll
        for (int off = 16; off > 0; off >>= 1)
            t += __shfl_xor_sync(0xffffffffu, t, off);
        if (lane == 0)
            out[r] = 1.f / (1.f + expf(-(t + l3_b[0]) * 1.5f));
    }
}

// ---------------------------------------------------------------------------
extern "C" void kernel_launch(void* const* d_in, const int* in_sizes, int n_in,
                              void* d_out, int out_size)
{
    const float* wf   = (const float*)d_in[0];
    const float* bf   = (const float*)d_in[1];
    const void*  side = d_in[2];
    const float* ft_w = (const float*)d_in[3];
    const float* ft_b = (const float*)d_in[4];
    const float* l1_w = (const float*)d_in[5];
    const float* l1_b = (const float*)d_in[6];
    const float* l2_w = (const float*)d_in[7];
    const float* l2_b = (const float*)d_in[8];
    const float* l3_w = (const float*)d_in[9];
    const float* l3_b = (const float*)d_in[10];
    float* out = (float*)d_out;

    k_prep<<<18, 256>>>((const unsigned int*)side, l1_w, l2_w);

    dim3 tgrid(N_IN / 32, H0 / 32);
    dim3 tblk(32, 8);
    k_transpose<<<tgrid, tblk>>>(ft_w);

    k_fused<<<B_ROWS, 256>>>(wf, bf, side, ft_b, l1_b, l2_b, l3_w, l3_b, out);
}